// round 15
// baseline (speedup 1.0000x reference)
#include <cuda_runtime.h>
#include <cuda_bf16.h>
#include <cstdint>

// ---------------------------------------------------------------------------
// Hierarchical PCN relaxation — fp8-dominant mma.sync mega-launch.
// v0/v1 frozen (E2 = v2 - r2[n] elementwise). NEW: incremental prediction —
//   pred(i+1) = pred(i) + dT2(i)@W2^T,  dT2 = tanh(v2') - tanh(v2) in fp8*256
// so the per-iteration eE3 GEMM is fp8 (half the bytes/instructions of bf16).
// Per iteration:
//   u2 (fp8):  v2 += DT*(-(v2-r2[n]) + (1-T2^2)*(E3@W2t));  emits T2b, dT2f
//   eE3 (fp8): v3 -= DT*E3*mask; pred += dT2@W2^T; E3 = v3 - pred
//              (mode 5 on last iter: also final sensory -> out)
// init: one bf16 GEMM computes E3(0) AND pred(0) = T2(0)@W2^T.
// Row-block dep counters + skew-8 row-group software pipeline (as R14).
// ---------------------------------------------------------------------------

using bf16 = __nv_bfloat16;

namespace {
constexpr int BROWS = 4096;
constexpr int D0 = 1024;
constexpr int D1 = 2048;
constexpr float DT_C = 0.01f;
constexpr float WSC = 32.0f;        // fp8 weight scale
constexpr float DSC = 256.0f;       // fp8 delta-T2 scale
constexpr float GS_U2 = 1.0f / 32.0f;
constexpr float GS_D = 1.0f / (256.0f * 32.0f);

constexpr int STAGES = 3;
constexpr int SROW = 144;
constexpr int TILE_B = 128 * SROW;
constexpr int STAGE_B = 2 * TILE_B;
constexpr int SMEM_BYTES = STAGES * STAGE_B;   // 110592

constexpr int NITER = 19;
constexpr int CPI = 1024;
constexpr int GRID_MEGA = 512 + NITER * CPI;   // 19968
constexpr int SK = 8;
constexpr int NCTR = 21 * 8 * 32;
}

// ------------------------- scratch (__device__ globals) --------------------
__device__ __align__(16) float g_v2[(size_t)BROWS * D1];
__device__ __align__(16) float g_v3[(size_t)BROWS * D1];
__device__ __align__(16) float g_E3[(size_t)BROWS * D1];
__device__ __align__(16) float g_pred[(size_t)BROWS * D1];
__device__ __align__(16) bf16 g_T2b[(size_t)BROWS * D1];
__device__ __align__(16) uint8_t g_E3f[(size_t)BROWS * D1];
__device__ __align__(16) uint8_t g_dT2f[(size_t)BROWS * D1];
__device__ __align__(16) bf16 g_W2b[(size_t)D1 * D1];
__device__ __align__(16) uint8_t g_W2f[(size_t)D1 * D1];    // fp8 *32, K-contig
__device__ __align__(16) uint8_t g_W2tf[(size_t)D1 * D1];   // fp8 *32, transposed
__device__ __align__(16) float g_row1[D1];
__device__ __align__(16) float g_row2[D1];
__device__ int g_ctr[NCTR];

// ------------------------------ helpers ------------------------------------
__device__ __forceinline__ void cp16(void* dst, const void* src) {
    uint32_t d = (uint32_t)__cvta_generic_to_shared(dst);
    asm volatile("cp.async.cg.shared.global [%0], [%1], 16;" :: "r"(d), "l"(src));
}
__device__ __forceinline__ void cp_commit() {
    asm volatile("cp.async.commit_group;" ::: "memory");
}
template <int N>
__device__ __forceinline__ void cp_wait() {
    asm volatile("cp.async.wait_group %0;" :: "n"(N) : "memory");
}
__device__ __forceinline__ void ldsm4(uint32_t* r, uint32_t addr) {
    asm volatile("ldmatrix.sync.aligned.m8n8.x4.shared.b16 {%0,%1,%2,%3}, [%4];"
                 : "=r"(r[0]), "=r"(r[1]), "=r"(r[2]), "=r"(r[3]) : "r"(addr));
}
__device__ __forceinline__ void mma_bf16(float* c, const uint32_t* a, const uint32_t* b) {
    asm volatile(
        "mma.sync.aligned.m16n8k16.row.col.f32.bf16.bf16.f32 "
        "{%0,%1,%2,%3}, {%4,%5,%6,%7}, {%8,%9}, {%0,%1,%2,%3};"
        : "+f"(c[0]), "+f"(c[1]), "+f"(c[2]), "+f"(c[3])
        : "r"(a[0]), "r"(a[1]), "r"(a[2]), "r"(a[3]), "r"(b[0]), "r"(b[1]));
}
__device__ __forceinline__ void mma_fp8(float* c, const uint32_t* a, const uint32_t* b) {
    asm volatile(
        "mma.sync.aligned.m16n8k32.row.col.f32.e4m3.e4m3.f32 "
        "{%0,%1,%2,%3}, {%4,%5,%6,%7}, {%8,%9}, {%0,%1,%2,%3};"
        : "+f"(c[0]), "+f"(c[1]), "+f"(c[2]), "+f"(c[3])
        : "r"(a[0]), "r"(a[1]), "r"(a[2]), "r"(a[3]), "r"(b[0]), "r"(b[1]));
}
__device__ __forceinline__ __nv_bfloat162 tobf2(float x, float y) {
    return __floats2bfloat162_rn(x, y);
}
__device__ __forceinline__ __nv_bfloat162 ldcg_bf2(const bf16* p) {
    unsigned int u = __ldcg((const unsigned int*)p);
    return *reinterpret_cast<__nv_bfloat162*>(&u);
}
__device__ __forceinline__ uint16_t f2e4m3x2(float lo, float hi) {
    uint16_t r;
    asm("cvt.rn.satfinite.e4m3x2.f32 %0, %1, %2;" : "=h"(r) : "f"(hi), "f"(lo));
    return r;
}
__device__ __forceinline__ uint8_t f2e4m3(float x) {
    return (uint8_t)f2e4m3x2(x, 0.f);
}

// ------------------------- sub-GEMM descriptor -----------------------------
// acc[m,n] = sum_k A[bm+m,k]*B[bn+n,k]
// mode 0 initE3 (bf16): E = X1 - acc; Out=E3, Xf=E3f, P=acc (pred init)
// mode 3 eE3 delta(fp8): vnew = X1 - DT*X3*Msk; OutV=vnew(v3);
//                        pnew = P + acc*gs -> P; E = vnew - pnew; Out=E3, Xf
// mode 5 final   (fp8):  vnew = X1 - DT*X3*Msk; pnew = P + acc*gs;
//                        E = vnew - pnew; Out = vnew - DT*E*Msk
// mode 1 u2      (fp8):  e = X1 - X3[n] (r2 row); deriv from Xb(old);
//                        nv -> Out(v2), Xb = tanh(nv), Xf = fp8((nt-told)*DSC)
struct Sub {
    const void *A, *B;
    const float* X1;
    bf16* Xb;
    uint8_t* Xf;
    const float* X3;
    const int* Msk;
    float* Out;
    float* OutV;
    float* P;
    int N, K, mode, nbx;
    float gs;
};

template <int ESZ>
__device__ __forceinline__ void gemm_core(const Sub& S, int lbid, char* smem) {
    const uint32_t sbase = (uint32_t)__cvta_generic_to_shared(smem);
    const int tid = threadIdx.x;
    const int bn = (lbid % S.nbx) * 128;
    const int bm = (lbid / S.nbx) * 128;
    const int K = S.K, N = S.N;
    const int rowb = K * ESZ;
    const char* gA = (const char*)S.A + (size_t)bm * rowb;
    const char* gB = (const char*)S.B + (size_t)bn * rowb;
    const int nkt = rowb / 128;

    const int warp = tid >> 5, lane = tid & 31;
    const int m0 = (warp & 3) * 32, n0 = (warp >> 2) * 64;
    const int g = lane >> 2, t4 = lane & 3;

    uint32_t aoff[2], boff[4];
#pragma unroll
    for (int mf = 0; mf < 2; mf++)
        aoff[mf] = (uint32_t)((m0 + mf * 16 + (lane & 15)) * SROW +
                              (lane >> 4) * 16);
#pragma unroll
    for (int nfp = 0; nfp < 4; nfp++)
        boff[nfp] = (uint32_t)((n0 + nfp * 16 + (lane & 7) +
                                ((lane >> 4) & 1) * 8) * SROW +
                               ((lane >> 3) & 1) * 16);

    int lrow[4], bcol[4];
#pragma unroll
    for (int i = 0; i < 4; i++) {
        const int c = tid + i * 256;
        lrow[i] = c >> 3;
        bcol[i] = (c & 7) * 16;
    }

    auto load_stage = [&](int s, int kt) {
        char* base = smem + s * STAGE_B;
        const char* a = gA + kt * 128;
        const char* b = gB + kt * 128;
#pragma unroll
        for (int i = 0; i < 4; i++) {
            cp16(base + lrow[i] * SROW + bcol[i],
                 a + (size_t)lrow[i] * rowb + bcol[i]);
            cp16(base + TILE_B + lrow[i] * SROW + bcol[i],
                 b + (size_t)lrow[i] * rowb + bcol[i]);
        }
    };

    float acc[2][8][4];
#pragma unroll
    for (int mf = 0; mf < 2; mf++)
#pragma unroll
        for (int nf = 0; nf < 8; nf++)
#pragma unroll
            for (int q = 0; q < 4; q++) acc[mf][nf][q] = 0.f;

#pragma unroll
    for (int s = 0; s < STAGES - 1; s++) { load_stage(s, s); cp_commit(); }

    for (int kt = 0; kt < nkt; kt++) {
        cp_wait<STAGES - 2>();
        __syncthreads();
        const int nl = kt + STAGES - 1;
        if (nl < nkt) load_stage(nl % STAGES, nl);
        cp_commit();

        const uint32_t sa = sbase + (uint32_t)((kt % STAGES) * STAGE_B);
        const uint32_t sb = sa + TILE_B;
#pragma unroll
        for (int ks = 0; ks < 4; ks++) {
            uint32_t af[2][4], bq[4][4];
            ldsm4(af[0], sa + aoff[0] + ks * 32);
            ldsm4(af[1], sa + aoff[1] + ks * 32);
#pragma unroll
            for (int nfp = 0; nfp < 4; nfp++)
                ldsm4(bq[nfp], sb + boff[nfp] + ks * 32);
#pragma unroll
            for (int mf = 0; mf < 2; mf++)
#pragma unroll
                for (int nf = 0; nf < 8; nf++) {
                    if (ESZ == 2)
                        mma_bf16(acc[mf][nf], af[mf], &bq[nf >> 1][(nf & 1) * 2]);
                    else
                        mma_fp8(acc[mf][nf], af[mf], &bq[nf >> 1][(nf & 1) * 2]);
                }
        }
    }

    // ------------------------------ epilogue -------------------------------
    const int mode = S.mode;
    const float gs = S.gs;
#pragma unroll
    for (int mf = 0; mf < 2; mf++) {
#pragma unroll
        for (int nf = 0; nf < 8; nf++) {
            const int m1 = bm + m0 + mf * 16 + g;
            const int nn = bn + n0 + nf * 8 + t4 * 2;
            const size_t i1 = (size_t)m1 * N + nn;
            const size_t i2 = (size_t)(m1 + 8) * N + nn;
            const float a0 = acc[mf][nf][0] * gs, a1 = acc[mf][nf][1] * gs;
            const float a2 = acc[mf][nf][2] * gs, a3 = acc[mf][nf][3] * gs;
            if (mode == 0) {
                // --- initE3 (bf16): E = v3 - acc; pred = acc ---
                float2 v1 = __ldcg((const float2*)(S.X1 + i1));
                float2 v2 = __ldcg((const float2*)(S.X1 + i2));
                float2 o1 = make_float2(v1.x - a0, v1.y - a1);
                float2 o2 = make_float2(v2.x - a2, v2.y - a3);
                *(float2*)(S.Out + i1) = o1;
                *(float2*)(S.Out + i2) = o2;
                *(uint16_t*)(S.Xf + i1) = f2e4m3x2(o1.x, o1.y);
                *(uint16_t*)(S.Xf + i2) = f2e4m3x2(o2.x, o2.y);
                *(float2*)(S.P + i1) = make_float2(a0, a1);
                *(float2*)(S.P + i2) = make_float2(a2, a3);
            } else if (mode == 3 || mode == 5) {
                // --- eE3 delta (fp8): pred += acc; E = v3' - pred ---
                float2 v1 = __ldcg((const float2*)(S.X1 + i1));
                float2 v2 = __ldcg((const float2*)(S.X1 + i2));
                float2 e1 = __ldcg((const float2*)(S.X3 + i1));
                float2 e2 = __ldcg((const float2*)(S.X3 + i2));
                int2 m1i = *(const int2*)(S.Msk + i1);
                int2 m2i = *(const int2*)(S.Msk + i2);
                v1.x -= DT_C * e1.x * (float)m1i.x;
                v1.y -= DT_C * e1.y * (float)m1i.y;
                v2.x -= DT_C * e2.x * (float)m2i.x;
                v2.y -= DT_C * e2.y * (float)m2i.y;
                float2 p1 = __ldcg((const float2*)(S.P + i1));
                float2 p2 = __ldcg((const float2*)(S.P + i2));
                p1.x += a0; p1.y += a1; p2.x += a2; p2.y += a3;
                float2 o1 = make_float2(v1.x - p1.x, v1.y - p1.y);
                float2 o2 = make_float2(v2.x - p2.x, v2.y - p2.y);
                if (mode == 3) {
                    *(float2*)(S.OutV + i1) = v1;
                    *(float2*)(S.OutV + i2) = v2;
                    *(float2*)(S.P + i1) = p1;
                    *(float2*)(S.P + i2) = p2;
                    *(float2*)(S.Out + i1) = o1;
                    *(float2*)(S.Out + i2) = o2;
                    *(uint16_t*)(S.Xf + i1) = f2e4m3x2(o1.x, o1.y);
                    *(uint16_t*)(S.Xf + i2) = f2e4m3x2(o2.x, o2.y);
                } else {
                    float2 w1, w2;
                    w1.x = v1.x - DT_C * o1.x * (float)m1i.x;
                    w1.y = v1.y - DT_C * o1.y * (float)m1i.y;
                    w2.x = v2.x - DT_C * o2.x * (float)m2i.x;
                    w2.y = v2.y - DT_C * o2.y * (float)m2i.y;
                    *(float2*)(S.Out + i1) = w1;
                    *(float2*)(S.Out + i2) = w2;
                }
            } else {
                // --- u2 (fp8): e = v2 - r2[n]; also emit dT2 fp8 ---
                float2 v1 = __ldcg((const float2*)(S.X1 + i1));
                float2 v2 = __ldcg((const float2*)(S.X1 + i2));
                __nv_bfloat162 tb1 = ldcg_bf2(S.Xb + i1);
                __nv_bfloat162 tb2 = ldcg_bf2(S.Xb + i2);
                float2 mm = *(const float2*)(S.X3 + nn);
                float vv[4] = {v1.x, v1.y, v2.x, v2.y};
                float tt[4] = {__bfloat162float(tb1.x), __bfloat162float(tb1.y),
                               __bfloat162float(tb2.x), __bfloat162float(tb2.y)};
                float ee[4] = {v1.x - mm.x, v1.y - mm.y, v2.x - mm.x, v2.y - mm.y};
                float aa[4] = {a0, a1, a2, a3};
                float nv[4], nt[4];
#pragma unroll
                for (int q = 0; q < 4; q++) {
                    const float deriv = 1.f - tt[q] * tt[q];
                    nv[q] = vv[q] + DT_C * (-ee[q] + deriv * aa[q]);
                    nt[q] = tanhf(nv[q]);
                }
                *(float2*)(S.Out + i1) = make_float2(nv[0], nv[1]);
                *(float2*)(S.Out + i2) = make_float2(nv[2], nv[3]);
                *(__nv_bfloat162*)(S.Xb + i1) = tobf2(nt[0], nt[1]);
                *(__nv_bfloat162*)(S.Xb + i2) = tobf2(nt[2], nt[3]);
                *(uint16_t*)(S.Xf + i1) =
                    f2e4m3x2((nt[0] - tt[0]) * DSC, (nt[1] - tt[1]) * DSC);
                *(uint16_t*)(S.Xf + i2) =
                    f2e4m3x2((nt[2] - tt[2]) * DSC, (nt[3] - tt[3]) * DSC);
            }
        }
    }
}

// --------------------------- mega kernel -----------------------------------
// Sub ids: 0=u2, 3=eE3(/mode5 last iter); init registered as (iter=-1, s=3).
struct MegaArgs {
    float *v2, *v3, *E3, *pred;
    bf16* T2b;
    uint8_t *E3f, *dT2f;
    const bf16* W2b;
    const uint8_t *W2f, *W2tf;
    const float* r2;
    const int* mask;
    float* out;
    int* ctr;
};

__device__ __forceinline__ int cidx(int iter, int s, int row) {
    return ((iter + 1) * 8 + s) * 32 + row;
}

__global__ void __launch_bounds__(256, 2)
gemm_mega(MegaArgs M) {
    extern __shared__ char smem[];
    const int bid = blockIdx.x;
    int iter, s, row, col;
    if (bid < 512) {
        iter = -1; s = 3; row = bid >> 4; col = bid & 15;
    } else {
        const int t0 = bid - 512;
        iter = t0 / CPI;
        int t = t0 % CPI;
        if (t < SK * 16) {
            s = 0; row = t >> 4; col = t & 15;
        } else if (t < SK * 16 + (32 - SK) * 32) {
            int q = t - SK * 16, gg = SK + q / 32, rem = q % 32;
            col = rem & 15;
            if (rem < 16) { s = 0; row = gg; }
            else          { s = 3; row = gg - SK; }
        } else {
            int q = t - (SK * 16 + (32 - SK) * 32);
            s = 3; row = 32 - SK + (q >> 4); col = q & 15;
        }
    }
    const int lb = row * 16 + col;

    // ---------------- row-granular dependency wait -------------------------
    int* C = M.ctr;
    int w1 = -1;
    if (iter >= 0) {
        if (s == 0) w1 = cidx(iter - 1, 3, row);   // u2 <- eE3(i-1)[row]
        else        w1 = cidx(iter, 0, row);       // eE3 <- u2(i)[row]
    }
    if (threadIdx.x == 0 && w1 >= 0)
        while (*(volatile int*)(C + w1) < 16) __nanosleep(64);
    __syncthreads();

    // ------------------------- build descriptor ----------------------------
    Sub S;
    if (s == 0) {        // u2 (fp8): G = E3@W2t
        S = {M.E3f, M.W2tf, M.v2, M.T2b, M.dT2f, M.r2, nullptr,
             M.v2, nullptr, nullptr, D1, D1, 1, 16, GS_U2};
    } else if (iter < 0) {   // initE3 (bf16): E3 + pred
        S = {M.T2b, M.W2b, M.v3, nullptr, M.E3f, nullptr, nullptr,
             M.E3, nullptr, M.pred, D1, D1, 0, 16, 1.f};
    } else if (iter == NITER - 1) {   // final (fp8 delta)
        S = {M.dT2f, M.W2f, M.v3, nullptr, nullptr, M.E3, M.mask,
             M.out, nullptr, M.pred, D1, D1, 5, 16, GS_D};
    } else {                          // eE3 delta (fp8)
        S = {M.dT2f, M.W2f, M.v3, nullptr, M.E3f, M.E3, M.mask,
             M.E3, M.v3, M.pred, D1, D1, 3, 16, GS_D};
    }

    if (iter < 0) gemm_core<2>(S, lb, smem);
    else          gemm_core<1>(S, lb, smem);

    // --------------------------- release -----------------------------------
    __threadfence();
    __syncthreads();
    if (threadIdx.x == 0) atomicAdd(C + cidx(iter, s, row), 1);
}

// --------------------------- small helper kernels --------------------------
__global__ void row_gemm(const float* __restrict__ in, const float* __restrict__ W,
                         float* __restrict__ out, int K) {
    const int n = blockIdx.x;
    float s = 0.f;
    for (int k = threadIdx.x; k < K; k += 256)
        s += tanhf(in[k]) * W[(size_t)n * K + k];
#pragma unroll
    for (int o = 16; o; o >>= 1) s += __shfl_down_sync(0xffffffffu, s, o);
    __shared__ float red[8];
    if ((threadIdx.x & 31) == 0) red[threadIdx.x >> 5] = s;
    __syncthreads();
    if (threadIdx.x == 0) {
        float t = 0.f;
#pragma unroll
        for (int w = 0; w < 8; w++) t += red[w];
        out[n] = t;
    }
}

__global__ void bcast2(const float* __restrict__ row, float* __restrict__ v,
                       bf16* __restrict__ t, int nmask, long total) {
    long i = (long)blockIdx.x * blockDim.x + threadIdx.x;
    const long stride = (long)gridDim.x * blockDim.x;
    for (; i < total; i += stride) {
        float x = row[i & nmask];
        v[i] = x;
        t[i] = __float2bfloat16_rn(tanhf(x));
    }
}

__global__ void zero_ctr(int* c, int n) {
    const int i = blockIdx.x * blockDim.x + threadIdx.x;
    if (i < n) c[i] = 0;
}

__global__ void round_copy(const float* __restrict__ in, bf16* __restrict__ out,
                           long total) {
    long i = (long)blockIdx.x * blockDim.x + threadIdx.x;
    const long stride = (long)gridDim.x * blockDim.x;
    for (; i < total; i += stride) out[i] = __float2bfloat16_rn(in[i]);
}

__global__ void round_f8(const float* __restrict__ in, uint8_t* __restrict__ out,
                         long total) {
    long i = (long)blockIdx.x * blockDim.x + threadIdx.x;
    const long stride = (long)gridDim.x * blockDim.x;
    for (; i < total; i += stride) out[i] = f2e4m3(in[i] * WSC);
}

__global__ void transpose_f8(const float* __restrict__ in, uint8_t* __restrict__ out,
                             int R, int C) {
    __shared__ float t[32][33];
    const int bx = blockIdx.x * 32, by = blockIdx.y * 32;
#pragma unroll
    for (int i = 0; i < 32; i += 8)
        t[threadIdx.y + i][threadIdx.x] =
            in[(size_t)(by + threadIdx.y + i) * C + bx + threadIdx.x];
    __syncthreads();
#pragma unroll
    for (int i = 0; i < 32; i += 8)
        out[(size_t)(bx + threadIdx.y + i) * R + by + threadIdx.x] =
            f2e4m3(t[threadIdx.x][threadIdx.y + i] * WSC);
}

// ------------------------------ orchestration ------------------------------
extern "C" void kernel_launch(void* const* d_in, const int* in_sizes, int n_in,
                              void* d_out, int out_size) {
    (void)in_sizes; (void)n_in; (void)out_size;
    const float* corrupt = (const float*)d_in[0];
    const float* memv    = (const float*)d_in[1];
    const float* W0      = (const float*)d_in[2];
    const float* W1      = (const float*)d_in[3];
    const float* W2      = (const float*)d_in[4];
    const int*   mask    = (const int*)d_in[5];
    float* out = (float*)d_out;

    MegaArgs M;
    int* ctr;
    float *r1, *r2;
    cudaGetSymbolAddress((void**)&M.v2, g_v2);
    cudaGetSymbolAddress((void**)&M.v3, g_v3);
    cudaGetSymbolAddress((void**)&M.E3, g_E3);
    cudaGetSymbolAddress((void**)&M.pred, g_pred);
    cudaGetSymbolAddress((void**)&ctr, g_ctr);
    cudaGetSymbolAddress((void**)&M.T2b, g_T2b);
    cudaGetSymbolAddress((void**)&M.E3f, g_E3f);
    cudaGetSymbolAddress((void**)&M.dT2f, g_dT2f);
    cudaGetSymbolAddress((void**)&M.W2b, g_W2b);
    cudaGetSymbolAddress((void**)&M.W2f, g_W2f);
    cudaGetSymbolAddress((void**)&M.W2tf, g_W2tf);
    cudaGetSymbolAddress((void**)&r1, g_row1);
    cudaGetSymbolAddress((void**)&r2, g_row2);
    M.r2 = r2; M.mask = mask; M.out = out; M.ctr = ctr;

    cudaFuncSetAttribute(gemm_mega, cudaFuncAttributeMaxDynamicSharedMemorySize,
                         SMEM_BYTES);

    // ------------------------------- init ----------------------------------
    round_copy<<<512, 256>>>(W2, (bf16*)M.W2b, (long)D1 * D1);
    round_f8<<<512, 256>>>(W2, (uint8_t*)M.W2f, (long)D1 * D1);
    const dim3 tb(32, 8);
    transpose_f8<<<dim3(D1 / 32, D1 / 32), tb>>>(W2, (uint8_t*)M.W2tf, D1, D1);

    row_gemm<<<D1, 256>>>(memv, W0, r1, D0);    // r1 = tanh(mem)@W0^T (v1 frozen)
    row_gemm<<<D1, 256>>>(r1, W1, r2, D1);      // r2 = tanh(r1)@W1^T
    bcast2<<<1024, 256>>>(r2, M.v2, M.T2b, D1 - 1, (long)BROWS * D1);
    cudaMemcpyAsync(M.v3, corrupt, sizeof(float) * (size_t)BROWS * D1,
                    cudaMemcpyDeviceToDevice, 0);
    zero_ctr<<<(NCTR + 255) / 256, 256>>>(ctr, NCTR);

    // --------------- everything else in ONE mega-launch --------------------
    gemm_mega<<<GRID_MEGA, 256, SMEM_BYTES>>>(M);
}

// round 16
// speedup vs baseline: 1.0948x; 1.0948x over previous
#include <cuda_runtime.h>
#include <cuda_bf16.h>
#include <cstdint>

// ---------------------------------------------------------------------------
// Hierarchical PCN relaxation — mixed bf16/fp8 mma.sync mega-launch (R14
// structure, fp8-delta experiment reverted).
// v0/v1 frozen at exact post-step-1 batch-uniform values:
//   E2 = v2 - r2[n] elementwise  (r2 = tanh(r1)@W1^T row)
//   E3(0) = corrupt - r3[n] elementwise (r3 = tanh(r2)@W2^T row) — the init
//   GEMM is gone; iteration 0 starts dependency-free.
// Per iteration (the only two GEMM subs):
//   u2  (fp8):  v2 += DT*(-(v2 - r2[n]) + (1-T2^2)*(E3@W2t))
//   eE3 (bf16): v3 -= DT*E3*mask;  E3 = v3 - T2@W2^T
//               (mode 5 on the last iteration also applies the final
//                sensory update and writes out directly)
// Row-block dep counters + skew-8 row-group software pipeline.
// ---------------------------------------------------------------------------

using bf16 = __nv_bfloat16;

namespace {
constexpr int BROWS = 4096;
constexpr int D0 = 1024;
constexpr int D1 = 2048;
constexpr float DT_C = 0.01f;
constexpr float WSC = 32.0f;
constexpr float WSC_INV = 1.0f / 32.0f;

constexpr int STAGES = 3;
constexpr int SROW = 144;
constexpr int TILE_B = 128 * SROW;
constexpr int STAGE_B = 2 * TILE_B;
constexpr int SMEM_BYTES = STAGES * STAGE_B;   // 110592

constexpr int NITER = 19;
constexpr int CPI = 1024;
constexpr int GRID_MEGA = NITER * CPI;         // 19456
constexpr int SK = 8;
constexpr int NCTR = 21 * 8 * 32;
}

// ------------------------- scratch (__device__ globals) --------------------
__device__ __align__(16) float g_v2[(size_t)BROWS * D1];
__device__ __align__(16) float g_v3[(size_t)BROWS * D1];
__device__ __align__(16) float g_E3[(size_t)BROWS * D1];
__device__ __align__(16) bf16 g_T2b[(size_t)BROWS * D1];
__device__ __align__(16) uint8_t g_E3f[(size_t)BROWS * D1];
__device__ __align__(16) bf16 g_W2b[(size_t)D1 * D1];
__device__ __align__(16) uint8_t g_W2tf[(size_t)D1 * D1];
__device__ __align__(16) float g_row1[D1];     // r1 = tanh(mem)@W0^T
__device__ __align__(16) float g_row2[D1];     // r2 = tanh(r1)@W1^T
__device__ __align__(16) float g_row3[D1];     // r3 = tanh(r2)@W2^T
__device__ int g_ctr[NCTR];

// ------------------------------ helpers ------------------------------------
__device__ __forceinline__ void cp16(void* dst, const void* src) {
    uint32_t d = (uint32_t)__cvta_generic_to_shared(dst);
    asm volatile("cp.async.cg.shared.global [%0], [%1], 16;" :: "r"(d), "l"(src));
}
__device__ __forceinline__ void cp_commit() {
    asm volatile("cp.async.commit_group;" ::: "memory");
}
template <int N>
__device__ __forceinline__ void cp_wait() {
    asm volatile("cp.async.wait_group %0;" :: "n"(N) : "memory");
}
__device__ __forceinline__ void ldsm4(uint32_t* r, uint32_t addr) {
    asm volatile("ldmatrix.sync.aligned.m8n8.x4.shared.b16 {%0,%1,%2,%3}, [%4];"
                 : "=r"(r[0]), "=r"(r[1]), "=r"(r[2]), "=r"(r[3]) : "r"(addr));
}
__device__ __forceinline__ void mma_bf16(float* c, const uint32_t* a, const uint32_t* b) {
    asm volatile(
        "mma.sync.aligned.m16n8k16.row.col.f32.bf16.bf16.f32 "
        "{%0,%1,%2,%3}, {%4,%5,%6,%7}, {%8,%9}, {%0,%1,%2,%3};"
        : "+f"(c[0]), "+f"(c[1]), "+f"(c[2]), "+f"(c[3])
        : "r"(a[0]), "r"(a[1]), "r"(a[2]), "r"(a[3]), "r"(b[0]), "r"(b[1]));
}
__device__ __forceinline__ void mma_fp8(float* c, const uint32_t* a, const uint32_t* b) {
    asm volatile(
        "mma.sync.aligned.m16n8k32.row.col.f32.e4m3.e4m3.f32 "
        "{%0,%1,%2,%3}, {%4,%5,%6,%7}, {%8,%9}, {%0,%1,%2,%3};"
        : "+f"(c[0]), "+f"(c[1]), "+f"(c[2]), "+f"(c[3])
        : "r"(a[0]), "r"(a[1]), "r"(a[2]), "r"(a[3]), "r"(b[0]), "r"(b[1]));
}
__device__ __forceinline__ __nv_bfloat162 tobf2(float x, float y) {
    return __floats2bfloat162_rn(x, y);
}
__device__ __forceinline__ __nv_bfloat162 ldcg_bf2(const bf16* p) {
    unsigned int u = __ldcg((const unsigned int*)p);
    return *reinterpret_cast<__nv_bfloat162*>(&u);
}
__device__ __forceinline__ uint16_t f2e4m3x2(float lo, float hi) {
    uint16_t r;
    asm("cvt.rn.satfinite.e4m3x2.f32 %0, %1, %2;" : "=h"(r) : "f"(hi), "f"(lo));
    return r;
}
__device__ __forceinline__ uint8_t f2e4m3(float x) {
    return (uint8_t)f2e4m3x2(x, 0.f);
}

// ------------------------- sub-GEMM descriptor -----------------------------
// acc[m,n] = sum_k A[bm+m,k]*B[bn+n,k]
// mode 3 eE3s (bf16): vnew = X1 - DT*X3*Msk; OutV=vnew(v3); E=vnew-acc;
//                     Out=E3 f32, Xf=fp8(E)
// mode 5 eE3fin:      vnew = X1 - DT*X3*Msk; E=vnew-acc; Out = vnew - DT*E*Msk
// mode 1 u2 (fp8):    e = X1 - X3[n] (r2 row); v' = v + DT*(-e + (1-T2^2)*acc*gs)
struct Sub {
    const void *A, *B;
    const float* X1;
    bf16* Xb;
    uint8_t* Xf;
    const float* X3;
    const int* Msk;
    float* Out;
    float* OutV;
    int N, K, mode, nbx;
    float gs;
};

template <int ESZ>
__device__ __forceinline__ void gemm_core(const Sub& S, int lbid, char* smem) {
    const uint32_t sbase = (uint32_t)__cvta_generic_to_shared(smem);
    const int tid = threadIdx.x;
    const int bn = (lbid % S.nbx) * 128;
    const int bm = (lbid / S.nbx) * 128;
    const int K = S.K, N = S.N;
    const int rowb = K * ESZ;
    const char* gA = (const char*)S.A + (size_t)bm * rowb;
    const char* gB = (const char*)S.B + (size_t)bn * rowb;
    const int nkt = rowb / 128;

    const int warp = tid >> 5, lane = tid & 31;
    const int m0 = (warp & 3) * 32, n0 = (warp >> 2) * 64;
    const int g = lane >> 2, t4 = lane & 3;

    uint32_t aoff[2], boff[4];
#pragma unroll
    for (int mf = 0; mf < 2; mf++)
        aoff[mf] = (uint32_t)((m0 + mf * 16 + (lane & 15)) * SROW +
                              (lane >> 4) * 16);
#pragma unroll
    for (int nfp = 0; nfp < 4; nfp++)
        boff[nfp] = (uint32_t)((n0 + nfp * 16 + (lane & 7) +
                                ((lane >> 4) & 1) * 8) * SROW +
                               ((lane >> 3) & 1) * 16);

    int lrow[4], bcol[4];
#pragma unroll
    for (int i = 0; i < 4; i++) {
        const int c = tid + i * 256;
        lrow[i] = c >> 3;
        bcol[i] = (c & 7) * 16;
    }

    auto load_stage = [&](int s, int kt) {
        char* base = smem + s * STAGE_B;
        const char* a = gA + kt * 128;
        const char* b = gB + kt * 128;
#pragma unroll
        for (int i = 0; i < 4; i++) {
            cp16(base + lrow[i] * SROW + bcol[i],
                 a + (size_t)lrow[i] * rowb + bcol[i]);
            cp16(base + TILE_B + lrow[i] * SROW + bcol[i],
                 b + (size_t)lrow[i] * rowb + bcol[i]);
        }
    };

    float acc[2][8][4];
#pragma unroll
    for (int mf = 0; mf < 2; mf++)
#pragma unroll
        for (int nf = 0; nf < 8; nf++)
#pragma unroll
            for (int q = 0; q < 4; q++) acc[mf][nf][q] = 0.f;

#pragma unroll
    for (int s = 0; s < STAGES - 1; s++) { load_stage(s, s); cp_commit(); }

    for (int kt = 0; kt < nkt; kt++) {
        cp_wait<STAGES - 2>();
        __syncthreads();
        const int nl = kt + STAGES - 1;
        if (nl < nkt) load_stage(nl % STAGES, nl);
        cp_commit();

        const uint32_t sa = sbase + (uint32_t)((kt % STAGES) * STAGE_B);
        const uint32_t sb = sa + TILE_B;
#pragma unroll
        for (int ks = 0; ks < 4; ks++) {
            uint32_t af[2][4], bq[4][4];
            ldsm4(af[0], sa + aoff[0] + ks * 32);
            ldsm4(af[1], sa + aoff[1] + ks * 32);
#pragma unroll
            for (int nfp = 0; nfp < 4; nfp++)
                ldsm4(bq[nfp], sb + boff[nfp] + ks * 32);
#pragma unroll
            for (int mf = 0; mf < 2; mf++)
#pragma unroll
                for (int nf = 0; nf < 8; nf++) {
                    if (ESZ == 2)
                        mma_bf16(acc[mf][nf], af[mf], &bq[nf >> 1][(nf & 1) * 2]);
                    else
                        mma_fp8(acc[mf][nf], af[mf], &bq[nf >> 1][(nf & 1) * 2]);
                }
        }
    }

    // ------------------------------ epilogue -------------------------------
    const int mode = S.mode;
    const float gs = S.gs;
#pragma unroll
    for (int mf = 0; mf < 2; mf++) {
#pragma unroll
        for (int nf = 0; nf < 8; nf++) {
            const int m1 = bm + m0 + mf * 16 + g;
            const int nn = bn + n0 + nf * 8 + t4 * 2;
            const size_t i1 = (size_t)m1 * N + nn;
            const size_t i2 = (size_t)(m1 + 8) * N + nn;
            const float a0 = acc[mf][nf][0] * gs, a1 = acc[mf][nf][1] * gs;
            const float a2 = acc[mf][nf][2] * gs, a3 = acc[mf][nf][3] * gs;
            if (mode != 1) {
                // --- err family (3 eE3s, 5 final) ---
                float2 v1 = __ldcg((const float2*)(S.X1 + i1));
                float2 v2 = __ldcg((const float2*)(S.X1 + i2));
                float2 e1 = __ldcg((const float2*)(S.X3 + i1));
                float2 e2 = __ldcg((const float2*)(S.X3 + i2));
                int2 m1i = *(const int2*)(S.Msk + i1);
                int2 m2i = *(const int2*)(S.Msk + i2);
                v1.x -= DT_C * e1.x * (float)m1i.x;
                v1.y -= DT_C * e1.y * (float)m1i.y;
                v2.x -= DT_C * e2.x * (float)m2i.x;
                v2.y -= DT_C * e2.y * (float)m2i.y;
                if (mode == 3) {
                    *(float2*)(S.OutV + i1) = v1;
                    *(float2*)(S.OutV + i2) = v2;
                }
                float2 o1 = make_float2(v1.x - a0, v1.y - a1);
                float2 o2 = make_float2(v2.x - a2, v2.y - a3);
                if (mode == 5) {
                    float2 w1, w2;
                    w1.x = v1.x - DT_C * o1.x * (float)m1i.x;
                    w1.y = v1.y - DT_C * o1.y * (float)m1i.y;
                    w2.x = v2.x - DT_C * o2.x * (float)m2i.x;
                    w2.y = v2.y - DT_C * o2.y * (float)m2i.y;
                    *(float2*)(S.Out + i1) = w1;
                    *(float2*)(S.Out + i2) = w2;
                } else {
                    *(float2*)(S.Out + i1) = o1;
                    *(float2*)(S.Out + i2) = o2;
                    *(uint16_t*)(S.Xf + i1) = f2e4m3x2(o1.x, o1.y);
                    *(uint16_t*)(S.Xf + i2) = f2e4m3x2(o2.x, o2.y);
                }
            } else {
                // --- u2 (fp8), row e-term: e = v2 - r2[n] ---
                float2 v1 = __ldcg((const float2*)(S.X1 + i1));
                float2 v2 = __ldcg((const float2*)(S.X1 + i2));
                __nv_bfloat162 tb1 = ldcg_bf2(S.Xb + i1);
                __nv_bfloat162 tb2 = ldcg_bf2(S.Xb + i2);
                float2 mm = *(const float2*)(S.X3 + nn);
                float vv[4] = {v1.x, v1.y, v2.x, v2.y};
                float tt[4] = {__bfloat162float(tb1.x), __bfloat162float(tb1.y),
                               __bfloat162float(tb2.x), __bfloat162float(tb2.y)};
                float ee[4] = {v1.x - mm.x, v1.y - mm.y, v2.x - mm.x, v2.y - mm.y};
                float aa[4] = {a0, a1, a2, a3};
                float nv[4], nt[4];
#pragma unroll
                for (int q = 0; q < 4; q++) {
                    const float deriv = 1.f - tt[q] * tt[q];
                    nv[q] = vv[q] + DT_C * (-ee[q] + deriv * aa[q]);
                    nt[q] = tanhf(nv[q]);
                }
                *(float2*)(S.Out + i1) = make_float2(nv[0], nv[1]);
                *(float2*)(S.Out + i2) = make_float2(nv[2], nv[3]);
                *(__nv_bfloat162*)(S.Xb + i1) = tobf2(nt[0], nt[1]);
                *(__nv_bfloat162*)(S.Xb + i2) = tobf2(nt[2], nt[3]);
            }
        }
    }
}

// --------------------------- mega kernel -----------------------------------
// Sub ids: 0=u2, 3=eE3s(/mode5 on last iter). No init sub — E3(0) is
// elementwise-precomputed (pred(0) is a single row r3).
// Counter index: ((iter+1)*8 + s)*32 + row.
struct MegaArgs {
    float *v2, *v3, *E3;
    bf16* T2b;
    uint8_t* E3f;
    const bf16* W2b;
    const uint8_t* W2tf;
    const float* r2;
    const int* mask;
    float* out;
    int* ctr;
};

__device__ __forceinline__ int cidx(int iter, int s, int row) {
    return ((iter + 1) * 8 + s) * 32 + row;
}

__global__ void __launch_bounds__(256, 2)
gemm_mega(MegaArgs M) {
    extern __shared__ char smem[];
    const int bid = blockIdx.x;
    const int iter = bid / CPI;
    int t = bid % CPI;
    int s, row, col;
    // skew-SK row groups: g<SK:[u2] | SK<=g<32:[u2,eE3s] | g>=32:[eE3s]
    if (t < SK * 16) {
        s = 0; row = t >> 4; col = t & 15;
    } else if (t < SK * 16 + (32 - SK) * 32) {
        int q = t - SK * 16, gg = SK + q / 32, rem = q % 32;
        col = rem & 15;
        if (rem < 16) { s = 0; row = gg; }
        else          { s = 3; row = gg - SK; }
    } else {
        int q = t - (SK * 16 + (32 - SK) * 32);
        s = 3; row = 32 - SK + (q >> 4); col = q & 15;
    }
    const int lb = row * 16 + col;

    // ---------------- row-granular dependency wait -------------------------
    int* C = M.ctr;
    int w1 = -1;
    if (s == 0) { if (iter > 0) w1 = cidx(iter - 1, 3, row); }  // u2 <- eE3(i-1)
    else        w1 = cidx(iter, 0, row);                        // eE3 <- u2(i)
    if (threadIdx.x == 0 && w1 >= 0)
        while (*(volatile int*)(C + w1) < 16) __nanosleep(64);
    __syncthreads();

    // ------------------------- build descriptor ----------------------------
    Sub S;
    if (s == 0) {        // u2 (fp8): G = E3@W2t; e = v2 - r2[n]
        S = {M.E3f, M.W2tf, M.v2, M.T2b, nullptr, M.r2, nullptr,
             M.v2, nullptr, D1, D1, 1, 16, WSC_INV};
    } else if (iter == NITER - 1) {   // final eE3 + double sensory -> out
        S = {M.T2b, M.W2b, M.v3, nullptr, nullptr, M.E3, M.mask,
             M.out, nullptr, D1, D1, 5, 16, 1.f};
    } else {                          // eE3s
        S = {M.T2b, M.W2b, M.v3, nullptr, M.E3f, M.E3, M.mask,
             M.E3, M.v3, D1, D1, 3, 16, 1.f};
    }

    if (s == 0) gemm_core<1>(S, lb, smem);
    else        gemm_core<2>(S, lb, smem);

    // --------------------------- release -----------------------------------
    __threadfence();
    __syncthreads();
    if (threadIdx.x == 0) atomicAdd(C + cidx(iter, s, row), 1);
}

// --------------------------- small helper kernels --------------------------
__global__ void row_gemm(const float* __restrict__ in, const float* __restrict__ W,
                         float* __restrict__ out, int K) {
    const int n = blockIdx.x;
    float s = 0.f;
    for (int k = threadIdx.x; k < K; k += 256)
        s += tanhf(in[k]) * W[(size_t)n * K + k];
#pragma unroll
    for (int o = 16; o; o >>= 1) s += __shfl_down_sync(0xffffffffu, s, o);
    __shared__ float red[8];
    if ((threadIdx.x & 31) == 0) red[threadIdx.x >> 5] = s;
    __syncthreads();
    if (threadIdx.x == 0) {
        float t = 0.f;
#pragma unroll
        for (int w = 0; w < 8; w++) t += red[w];
        out[n] = t;
    }
}

__global__ void bcast2(const float* __restrict__ row, float* __restrict__ v,
                       bf16* __restrict__ t, int nmask, long total) {
    long i = (long)blockIdx.x * blockDim.x + threadIdx.x;
    const long stride = (long)gridDim.x * blockDim.x;
    for (; i < total; i += stride) {
        float x = row[i & nmask];
        v[i] = x;
        t[i] = __float2bfloat16_rn(tanhf(x));
    }
}

// v3 = corrupt; E3 = corrupt - r3[n]; E3f = fp8(E3)   (pred(0) is row r3)
__global__ void e3_init(const float* __restrict__ corrupt,
                        const float* __restrict__ r3, float* __restrict__ v3,
                        float* __restrict__ E3, uint8_t* __restrict__ E3f,
                        int nmask, long total) {
    long i = (long)blockIdx.x * blockDim.x + threadIdx.x;
    const long stride = (long)gridDim.x * blockDim.x;
    for (; i < total; i += stride) {
        float c = corrupt[i];
        float e = c - r3[i & nmask];
        v3[i] = c;
        E3[i] = e;
        E3f[i] = f2e4m3(e);
    }
}

__global__ void zero_ctr(int* c, int n) {
    const int i = blockIdx.x * blockDim.x + threadIdx.x;
    if (i < n) c[i] = 0;
}

__global__ void round_copy(const float* __restrict__ in, bf16* __restrict__ out,
                           long total) {
    long i = (long)blockIdx.x * blockDim.x + threadIdx.x;
    const long stride = (long)gridDim.x * blockDim.x;
    for (; i < total; i += stride) out[i] = __float2bfloat16_rn(in[i]);
}

__global__ void transpose_f8(const float* __restrict__ in, uint8_t* __restrict__ out,
                             int R, int C) {
    __shared__ float t[32][33];
    const int bx = blockIdx.x * 32, by = blockIdx.y * 32;
#pragma unroll
    for (int i = 0; i < 32; i += 8)
        t[threadIdx.y + i][threadIdx.x] =
            in[(size_t)(by + threadIdx.y + i) * C + bx + threadIdx.x];
    __syncthreads();
#pragma unroll
    for (int i = 0; i < 32; i += 8)
        out[(size_t)(bx + threadIdx.y + i) * R + by + threadIdx.x] =
            f2e4m3(t[threadIdx.x][threadIdx.y + i] * WSC);
}

// ------------------------------ orchestration ------------------------------
extern "C" void kernel_launch(void* const* d_in, const int* in_sizes, int n_in,
                              void* d_out, int out_size) {
    (void)in_sizes; (void)n_in; (void)out_size;
    const float* corrupt = (const float*)d_in[0];
    const float* memv    = (const float*)d_in[1];
    const float* W0      = (const float*)d_in[2];
    const float* W1      = (const float*)d_in[3];
    const float* W2      = (const float*)d_in[4];
    const int*   mask    = (const int*)d_in[5];
    float* out = (float*)d_out;

    MegaArgs M;
    int* ctr;
    float *r1, *r2, *r3;
    cudaGetSymbolAddress((void**)&M.v2, g_v2);
    cudaGetSymbolAddress((void**)&M.v3, g_v3);
    cudaGetSymbolAddress((void**)&M.E3, g_E3);
    cudaGetSymbolAddress((void**)&ctr, g_ctr);
    cudaGetSymbolAddress((void**)&M.T2b, g_T2b);
    cudaGetSymbolAddress((void**)&M.E3f, g_E3f);
    cudaGetSymbolAddress((void**)&M.W2b, g_W2b);
    cudaGetSymbolAddress((void**)&M.W2tf, g_W2tf);
    cudaGetSymbolAddress((void**)&r1, g_row1);
    cudaGetSymbolAddress((void**)&r2, g_row2);
    cudaGetSymbolAddress((void**)&r3, g_row3);
    M.r2 = r2; M.mask = mask; M.out = out; M.ctr = ctr;

    cudaFuncSetAttribute(gemm_mega, cudaFuncAttributeMaxDynamicSharedMemorySize,
                         SMEM_BYTES);

    // ------------------------------- init ----------------------------------
    round_copy<<<512, 256>>>(W2, (bf16*)M.W2b, (long)D1 * D1);
    const dim3 tb(32, 8);
    transpose_f8<<<dim3(D1 / 32, D1 / 32), tb>>>(W2, (uint8_t*)M.W2tf, D1, D1);

    row_gemm<<<D1, 256>>>(memv, W0, r1, D0);    // r1 = tanh(mem)@W0^T (v1 frozen)
    row_gemm<<<D1, 256>>>(r1, W1, r2, D1);      // r2 = tanh(r1)@W1^T  (v2(0) row)
    row_gemm<<<D1, 256>>>(r2, W2, r3, D1);      // r3 = tanh(r2)@W2^T  (pred(0) row)
    bcast2<<<1024, 256>>>(r2, M.v2, M.T2b, D1 - 1, (long)BROWS * D1);
    e3_init<<<1024, 256>>>(corrupt, r3, M.v3, M.E3, M.E3f, D1 - 1,
                           (long)BROWS * D1);
    zero_ctr<<<(NCTR + 255) / 256, 256>>>(ctr, NCTR);

    // --------------- the whole 19-iteration loop in ONE launch -------------
    gemm_mega<<<GRID_MEGA, 256, SMEM_BYTES>>>(M);
}

// round 17
// speedup vs baseline: 1.0979x; 1.0029x over previous
#include <cuda_runtime.h>
#include <cuda_bf16.h>
#include <cstdint>

// ---------------------------------------------------------------------------
// Hierarchical PCN relaxation — mixed bf16/fp8 mma.sync mega-launch.
// v0/v1 frozen at exact post-step-1 batch-uniform values:
//   E2 = v2 - r2[n] elementwise  (r2 = tanh(r1)@W1^T row)
//   E3(0) = corrupt - r3[n] elementwise (r3 = tanh(r2)@W2^T row)
//   v2(0) = r2[n] broadcast — folded into u2(iter 0)'s epilogue (mode 2:
//   e = 0 exactly, v/tanh read from the r2 row), deleting the 32MB bcast.
// Per iteration (the only two GEMM subs):
//   u2  (fp8):  v2 += DT*(-(v2 - r2[n]) + (1-T2^2)*(E3@W2t))
//   eE3 (bf16): v3 -= DT*E3*mask;  E3 = v3 - T2@W2^T
//               (mode 5 on the last iteration also applies the final
//                sensory update and writes out directly)
// Row-block dep counters + skew-8 row-group software pipeline.
// ---------------------------------------------------------------------------

using bf16 = __nv_bfloat16;

namespace {
constexpr int BROWS = 4096;
constexpr int D0 = 1024;
constexpr int D1 = 2048;
constexpr float DT_C = 0.01f;
constexpr float WSC = 32.0f;
constexpr float WSC_INV = 1.0f / 32.0f;

constexpr int STAGES = 3;
constexpr int SROW = 144;
constexpr int TILE_B = 128 * SROW;
constexpr int STAGE_B = 2 * TILE_B;
constexpr int SMEM_BYTES = STAGES * STAGE_B;   // 110592

constexpr int NITER = 19;
constexpr int CPI = 1024;
constexpr int GRID_MEGA = NITER * CPI;         // 19456
constexpr int SK = 8;
constexpr int NCTR = 21 * 8 * 32;
}

// ------------------------- scratch (__device__ globals) --------------------
__device__ __align__(16) float g_v2[(size_t)BROWS * D1];
__device__ __align__(16) float g_v3[(size_t)BROWS * D1];
__device__ __align__(16) float g_E3[(size_t)BROWS * D1];
__device__ __align__(16) bf16 g_T2b[(size_t)BROWS * D1];
__device__ __align__(16) uint8_t g_E3f[(size_t)BROWS * D1];
__device__ __align__(16) bf16 g_W2b[(size_t)D1 * D1];
__device__ __align__(16) uint8_t g_W2tf[(size_t)D1 * D1];
__device__ __align__(16) float g_row1[D1];     // r1 = tanh(mem)@W0^T
__device__ __align__(16) float g_row2[D1];     // r2 = tanh(r1)@W1^T
__device__ __align__(16) float g_row3[D1];     // r3 = tanh(r2)@W2^T
__device__ int g_ctr[NCTR];

// ------------------------------ helpers ------------------------------------
__device__ __forceinline__ void cp16(void* dst, const void* src) {
    uint32_t d = (uint32_t)__cvta_generic_to_shared(dst);
    asm volatile("cp.async.cg.shared.global [%0], [%1], 16;" :: "r"(d), "l"(src));
}
__device__ __forceinline__ void cp_commit() {
    asm volatile("cp.async.commit_group;" ::: "memory");
}
template <int N>
__device__ __forceinline__ void cp_wait() {
    asm volatile("cp.async.wait_group %0;" :: "n"(N) : "memory");
}
__device__ __forceinline__ void ldsm4(uint32_t* r, uint32_t addr) {
    asm volatile("ldmatrix.sync.aligned.m8n8.x4.shared.b16 {%0,%1,%2,%3}, [%4];"
                 : "=r"(r[0]), "=r"(r[1]), "=r"(r[2]), "=r"(r[3]) : "r"(addr));
}
__device__ __forceinline__ void mma_bf16(float* c, const uint32_t* a, const uint32_t* b) {
    asm volatile(
        "mma.sync.aligned.m16n8k16.row.col.f32.bf16.bf16.f32 "
        "{%0,%1,%2,%3}, {%4,%5,%6,%7}, {%8,%9}, {%0,%1,%2,%3};"
        : "+f"(c[0]), "+f"(c[1]), "+f"(c[2]), "+f"(c[3])
        : "r"(a[0]), "r"(a[1]), "r"(a[2]), "r"(a[3]), "r"(b[0]), "r"(b[1]));
}
__device__ __forceinline__ void mma_fp8(float* c, const uint32_t* a, const uint32_t* b) {
    asm volatile(
        "mma.sync.aligned.m16n8k32.row.col.f32.e4m3.e4m3.f32 "
        "{%0,%1,%2,%3}, {%4,%5,%6,%7}, {%8,%9}, {%0,%1,%2,%3};"
        : "+f"(c[0]), "+f"(c[1]), "+f"(c[2]), "+f"(c[3])
        : "r"(a[0]), "r"(a[1]), "r"(a[2]), "r"(a[3]), "r"(b[0]), "r"(b[1]));
}
__device__ __forceinline__ __nv_bfloat162 tobf2(float x, float y) {
    return __floats2bfloat162_rn(x, y);
}
__device__ __forceinline__ __nv_bfloat162 ldcg_bf2(const bf16* p) {
    unsigned int u = __ldcg((const unsigned int*)p);
    return *reinterpret_cast<__nv_bfloat162*>(&u);
}
__device__ __forceinline__ uint16_t f2e4m3x2(float lo, float hi) {
    uint16_t r;
    asm("cvt.rn.satfinite.e4m3x2.f32 %0, %1, %2;" : "=h"(r) : "f"(hi), "f"(lo));
    return r;
}
__device__ __forceinline__ uint8_t f2e4m3(float x) {
    return (uint8_t)f2e4m3x2(x, 0.f);
}

// ------------------------- sub-GEMM descriptor -----------------------------
// acc[m,n] = sum_k A[bm+m,k]*B[bn+n,k]
// mode 3 eE3s (bf16): vnew = X1 - DT*X3*Msk; OutV=vnew(v3); E=vnew-acc;
//                     Out=E3 f32, Xf=fp8(E)
// mode 5 eE3fin:      vnew = X1 - DT*X3*Msk; E=vnew-acc; Out = vnew - DT*E*Msk
// mode 1 u2 (fp8):    e = X1 - X3[n] (r2 row); v' = v + DT*(-e + (1-T2^2)*acc*gs)
// mode 2 u2 iter0:    v = X3[n] (r2 row), e = 0 exactly, tanh inline
struct Sub {
    const void *A, *B;
    const float* X1;
    bf16* Xb;
    uint8_t* Xf;
    const float* X3;
    const int* Msk;
    float* Out;
    float* OutV;
    int N, K, mode, nbx;
    float gs;
};

template <int ESZ>
__device__ __forceinline__ void gemm_core(const Sub& S, int lbid, char* smem) {
    const uint32_t sbase = (uint32_t)__cvta_generic_to_shared(smem);
    const int tid = threadIdx.x;
    const int bn = (lbid % S.nbx) * 128;
    const int bm = (lbid / S.nbx) * 128;
    const int K = S.K, N = S.N;
    const int rowb = K * ESZ;
    const char* gA = (const char*)S.A + (size_t)bm * rowb;
    const char* gB = (const char*)S.B + (size_t)bn * rowb;
    const int nkt = rowb / 128;

    const int warp = tid >> 5, lane = tid & 31;
    const int m0 = (warp & 3) * 32, n0 = (warp >> 2) * 64;
    const int g = lane >> 2, t4 = lane & 3;

    uint32_t aoff[2], boff[4];
#pragma unroll
    for (int mf = 0; mf < 2; mf++)
        aoff[mf] = (uint32_t)((m0 + mf * 16 + (lane & 15)) * SROW +
                              (lane >> 4) * 16);
#pragma unroll
    for (int nfp = 0; nfp < 4; nfp++)
        boff[nfp] = (uint32_t)((n0 + nfp * 16 + (lane & 7) +
                                ((lane >> 4) & 1) * 8) * SROW +
                               ((lane >> 3) & 1) * 16);

    int lrow[4], bcol[4];
#pragma unroll
    for (int i = 0; i < 4; i++) {
        const int c = tid + i * 256;
        lrow[i] = c >> 3;
        bcol[i] = (c & 7) * 16;
    }

    auto load_stage = [&](int s, int kt) {
        char* base = smem + s * STAGE_B;
        const char* a = gA + kt * 128;
        const char* b = gB + kt * 128;
#pragma unroll
        for (int i = 0; i < 4; i++) {
            cp16(base + lrow[i] * SROW + bcol[i],
                 a + (size_t)lrow[i] * rowb + bcol[i]);
            cp16(base + TILE_B + lrow[i] * SROW + bcol[i],
                 b + (size_t)lrow[i] * rowb + bcol[i]);
        }
    };

    float acc[2][8][4];
#pragma unroll
    for (int mf = 0; mf < 2; mf++)
#pragma unroll
        for (int nf = 0; nf < 8; nf++)
#pragma unroll
            for (int q = 0; q < 4; q++) acc[mf][nf][q] = 0.f;

#pragma unroll
    for (int s = 0; s < STAGES - 1; s++) { load_stage(s, s); cp_commit(); }

    for (int kt = 0; kt < nkt; kt++) {
        cp_wait<STAGES - 2>();
        __syncthreads();
        const int nl = kt + STAGES - 1;
        if (nl < nkt) load_stage(nl % STAGES, nl);
        cp_commit();

        const uint32_t sa = sbase + (uint32_t)((kt % STAGES) * STAGE_B);
        const uint32_t sb = sa + TILE_B;
#pragma unroll
        for (int ks = 0; ks < 4; ks++) {
            uint32_t af[2][4], bq[4][4];
            ldsm4(af[0], sa + aoff[0] + ks * 32);
            ldsm4(af[1], sa + aoff[1] + ks * 32);
#pragma unroll
            for (int nfp = 0; nfp < 4; nfp++)
                ldsm4(bq[nfp], sb + boff[nfp] + ks * 32);
#pragma unroll
            for (int mf = 0; mf < 2; mf++)
#pragma unroll
                for (int nf = 0; nf < 8; nf++) {
                    if (ESZ == 2)
                        mma_bf16(acc[mf][nf], af[mf], &bq[nf >> 1][(nf & 1) * 2]);
                    else
                        mma_fp8(acc[mf][nf], af[mf], &bq[nf >> 1][(nf & 1) * 2]);
                }
        }
    }

    // ------------------------------ epilogue -------------------------------
    const int mode = S.mode;
    const float gs = S.gs;
#pragma unroll
    for (int mf = 0; mf < 2; mf++) {
#pragma unroll
        for (int nf = 0; nf < 8; nf++) {
            const int m1 = bm + m0 + mf * 16 + g;
            const int nn = bn + n0 + nf * 8 + t4 * 2;
            const size_t i1 = (size_t)m1 * N + nn;
            const size_t i2 = (size_t)(m1 + 8) * N + nn;
            const float a0 = acc[mf][nf][0] * gs, a1 = acc[mf][nf][1] * gs;
            const float a2 = acc[mf][nf][2] * gs, a3 = acc[mf][nf][3] * gs;
            if (mode == 3 || mode == 5) {
                // --- err family (3 eE3s, 5 final) ---
                float2 v1 = __ldcg((const float2*)(S.X1 + i1));
                float2 v2 = __ldcg((const float2*)(S.X1 + i2));
                float2 e1 = __ldcg((const float2*)(S.X3 + i1));
                float2 e2 = __ldcg((const float2*)(S.X3 + i2));
                int2 m1i = *(const int2*)(S.Msk + i1);
                int2 m2i = *(const int2*)(S.Msk + i2);
                v1.x -= DT_C * e1.x * (float)m1i.x;
                v1.y -= DT_C * e1.y * (float)m1i.y;
                v2.x -= DT_C * e2.x * (float)m2i.x;
                v2.y -= DT_C * e2.y * (float)m2i.y;
                if (mode == 3) {
                    *(float2*)(S.OutV + i1) = v1;
                    *(float2*)(S.OutV + i2) = v2;
                }
                float2 o1 = make_float2(v1.x - a0, v1.y - a1);
                float2 o2 = make_float2(v2.x - a2, v2.y - a3);
                if (mode == 5) {
                    float2 w1, w2;
                    w1.x = v1.x - DT_C * o1.x * (float)m1i.x;
                    w1.y = v1.y - DT_C * o1.y * (float)m1i.y;
                    w2.x = v2.x - DT_C * o2.x * (float)m2i.x;
                    w2.y = v2.y - DT_C * o2.y * (float)m2i.y;
                    *(float2*)(S.Out + i1) = w1;
                    *(float2*)(S.Out + i2) = w2;
                } else {
                    *(float2*)(S.Out + i1) = o1;
                    *(float2*)(S.Out + i2) = o2;
                    *(uint16_t*)(S.Xf + i1) = f2e4m3x2(o1.x, o1.y);
                    *(uint16_t*)(S.Xf + i2) = f2e4m3x2(o2.x, o2.y);
                }
            } else {
                // --- u2 (fp8): mode 1 normal, mode 2 iter-0 (v=r2[n], e=0) ---
                float2 mm = *(const float2*)(S.X3 + nn);   // r2 row
                float vv[4], tt[4], ee[4];
                if (mode == 1) {
                    float2 v1 = __ldcg((const float2*)(S.X1 + i1));
                    float2 v2 = __ldcg((const float2*)(S.X1 + i2));
                    __nv_bfloat162 tb1 = ldcg_bf2(S.Xb + i1);
                    __nv_bfloat162 tb2 = ldcg_bf2(S.Xb + i2);
                    vv[0] = v1.x; vv[1] = v1.y; vv[2] = v2.x; vv[3] = v2.y;
                    tt[0] = __bfloat162float(tb1.x); tt[1] = __bfloat162float(tb1.y);
                    tt[2] = __bfloat162float(tb2.x); tt[3] = __bfloat162float(tb2.y);
                    ee[0] = v1.x - mm.x; ee[1] = v1.y - mm.y;
                    ee[2] = v2.x - mm.x; ee[3] = v2.y - mm.y;
                } else {   // mode 2: batch-uniform start, e = 0 exactly
                    vv[0] = mm.x; vv[1] = mm.y; vv[2] = mm.x; vv[3] = mm.y;
                    tt[0] = tanhf(mm.x); tt[1] = tanhf(mm.y);
                    tt[2] = tt[0];       tt[3] = tt[1];
                    ee[0] = ee[1] = ee[2] = ee[3] = 0.f;
                }
                float aa[4] = {a0, a1, a2, a3};
                float nv[4], nt[4];
#pragma unroll
                for (int q = 0; q < 4; q++) {
                    const float deriv = 1.f - tt[q] * tt[q];
                    nv[q] = vv[q] + DT_C * (-ee[q] + deriv * aa[q]);
                    nt[q] = tanhf(nv[q]);
                }
                *(float2*)(S.Out + i1) = make_float2(nv[0], nv[1]);
                *(float2*)(S.Out + i2) = make_float2(nv[2], nv[3]);
                *(__nv_bfloat162*)(S.Xb + i1) = tobf2(nt[0], nt[1]);
                *(__nv_bfloat162*)(S.Xb + i2) = tobf2(nt[2], nt[3]);
            }
        }
    }
}

// --------------------------- mega kernel -----------------------------------
// Sub ids: 0=u2, 3=eE3s(/mode5 on last iter). No init sub, no bcast —
// E3(0) elementwise-precomputed; v2(0)/T2(0) synthesized in u2(0)'s epilogue.
// Counter index: ((iter+1)*8 + s)*32 + row.
struct MegaArgs {
    float *v2, *v3, *E3;
    bf16* T2b;
    uint8_t* E3f;
    const bf16* W2b;
    const uint8_t* W2tf;
    const float* r2;
    const int* mask;
    float* out;
    int* ctr;
};

__device__ __forceinline__ int cidx(int iter, int s, int row) {
    return ((iter + 1) * 8 + s) * 32 + row;
}

__global__ void __launch_bounds__(256, 2)
gemm_mega(MegaArgs M) {
    extern __shared__ char smem[];
    const int bid = blockIdx.x;
    const int iter = bid / CPI;
    int t = bid % CPI;
    int s, row, col;
    // skew-SK row groups: g<SK:[u2] | SK<=g<32:[u2,eE3s] | g>=32:[eE3s]
    if (t < SK * 16) {
        s = 0; row = t >> 4; col = t & 15;
    } else if (t < SK * 16 + (32 - SK) * 32) {
        int q = t - SK * 16, gg = SK + q / 32, rem = q % 32;
        col = rem & 15;
        if (rem < 16) { s = 0; row = gg; }
        else          { s = 3; row = gg - SK; }
    } else {
        int q = t - (SK * 16 + (32 - SK) * 32);
        s = 3; row = 32 - SK + (q >> 4); col = q & 15;
    }
    const int lb = row * 16 + col;

    // ---------------- row-granular dependency wait -------------------------
    int* C = M.ctr;
    int w1 = -1;
    if (s == 0) { if (iter > 0) w1 = cidx(iter - 1, 3, row); }  // u2 <- eE3(i-1)
    else        w1 = cidx(iter, 0, row);                        // eE3 <- u2(i)
    if (threadIdx.x == 0 && w1 >= 0)
        while (*(volatile int*)(C + w1) < 16) __nanosleep(64);
    __syncthreads();

    // ------------------------- build descriptor ----------------------------
    Sub S;
    if (s == 0) {        // u2 (fp8): G = E3@W2t
        S = {M.E3f, M.W2tf, M.v2, M.T2b, nullptr, M.r2, nullptr,
             M.v2, nullptr, D1, D1, (iter == 0) ? 2 : 1, 16, WSC_INV};
    } else if (iter == NITER - 1) {   // final eE3 + double sensory -> out
        S = {M.T2b, M.W2b, M.v3, nullptr, nullptr, M.E3, M.mask,
             M.out, nullptr, D1, D1, 5, 16, 1.f};
    } else {                          // eE3s
        S = {M.T2b, M.W2b, M.v3, nullptr, M.E3f, M.E3, M.mask,
             M.E3, M.v3, D1, D1, 3, 16, 1.f};
    }

    if (s == 0) gemm_core<1>(S, lb, smem);
    else        gemm_core<2>(S, lb, smem);

    // --------------------------- release -----------------------------------
    __threadfence();
    __syncthreads();
    if (threadIdx.x == 0) atomicAdd(C + cidx(iter, s, row), 1);
}

// --------------------------- small helper kernels --------------------------
__global__ void row_gemm(const float* __restrict__ in, const float* __restrict__ W,
                         float* __restrict__ out, int K) {
    const int n = blockIdx.x;
    float s = 0.f;
    for (int k = threadIdx.x; k < K; k += 256)
        s += tanhf(in[k]) * W[(size_t)n * K + k];
#pragma unroll
    for (int o = 16; o; o >>= 1) s += __shfl_down_sync(0xffffffffu, s, o);
    __shared__ float red[8];
    if ((threadIdx.x & 31) == 0) red[threadIdx.x >> 5] = s;
    __syncthreads();
    if (threadIdx.x == 0) {
        float t = 0.f;
#pragma unroll
        for (int w = 0; w < 8; w++) t += red[w];
        out[n] = t;
    }
}

// v3 = corrupt; E3 = corrupt - r3[n]; E3f = fp8(E3)   (pred(0) is row r3)
__global__ void e3_init(const float* __restrict__ corrupt,
                        const float* __restrict__ r3, float* __restrict__ v3,
                        float* __restrict__ E3, uint8_t* __restrict__ E3f,
                        int nmask, long total) {
    long i = (long)blockIdx.x * blockDim.x + threadIdx.x;
    const long stride = (long)gridDim.x * blockDim.x;
    for (; i < total; i += stride) {
        float c = corrupt[i];
        float e = c - r3[i & nmask];
        v3[i] = c;
        E3[i] = e;
        E3f[i] = f2e4m3(e);
    }
}

__global__ void zero_ctr(int* c, int n) {
    const int i = blockIdx.x * blockDim.x + threadIdx.x;
    if (i < n) c[i] = 0;
}

__global__ void round_copy(const float* __restrict__ in, bf16* __restrict__ out,
                           long total) {
    long i = (long)blockIdx.x * blockDim.x + threadIdx.x;
    const long stride = (long)gridDim.x * blockDim.x;
    for (; i < total; i += stride) out[i] = __float2bfloat16_rn(in[i]);
}

__global__ void transpose_f8(const float* __restrict__ in, uint8_t* __restrict__ out,
                             int R, int C) {
    __shared__ float t[32][33];
    const int bx = blockIdx.x * 32, by = blockIdx.y * 32;
#pragma unroll
    for (int i = 0; i < 32; i += 8)
        t[threadIdx.y + i][threadIdx.x] =
            in[(size_t)(by + threadIdx.y + i) * C + bx + threadIdx.x];
    __syncthreads();
#pragma unroll
    for (int i = 0; i < 32; i += 8)
        out[(size_t)(bx + threadIdx.y + i) * R + by + threadIdx.x] =
            f2e4m3(t[threadIdx.x][threadIdx.y + i] * WSC);
}

// ------------------------------ orchestration ------------------------------
extern "C" void kernel_launch(void* const* d_in, const int* in_sizes, int n_in,
                              void* d_out, int out_size) {
    (void)in_sizes; (void)n_in; (void)out_size;
    const float* corrupt = (const float*)d_in[0];
    const float* memv    = (const float*)d_in[1];
    const float* W0      = (const float*)d_in[2];
    const float* W1      = (const float*)d_in[3];
    const float* W2      = (const float*)d_in[4];
    const int*   mask    = (const int*)d_in[5];
    float* out = (float*)d_out;

    MegaArgs M;
    int* ctr;
    float *r1, *r2, *r3;
    cudaGetSymbolAddress((void**)&M.v2, g_v2);
    cudaGetSymbolAddress((void**)&M.v3, g_v3);
    cudaGetSymbolAddress((void**)&M.E3, g_E3);
    cudaGetSymbolAddress((void**)&ctr, g_ctr);
    cudaGetSymbolAddress((void**)&M.T2b, g_T2b);
    cudaGetSymbolAddress((void**)&M.E3f, g_E3f);
    cudaGetSymbolAddress((void**)&M.W2b, g_W2b);
    cudaGetSymbolAddress((void**)&M.W2tf, g_W2tf);
    cudaGetSymbolAddress((void**)&r1, g_row1);
    cudaGetSymbolAddress((void**)&r2, g_row2);
    cudaGetSymbolAddress((void**)&r3, g_row3);
    M.r2 = r2; M.mask = mask; M.out = out; M.ctr = ctr;

    cudaFuncSetAttribute(gemm_mega, cudaFuncAttributeMaxDynamicSharedMemorySize,
                         SMEM_BYTES);

    // ------------------------------- init ----------------------------------
    round_copy<<<512, 256>>>(W2, (bf16*)M.W2b, (long)D1 * D1);
    const dim3 tb(32, 8);
    transpose_f8<<<dim3(D1 / 32, D1 / 32), tb>>>(W2, (uint8_t*)M.W2tf, D1, D1);

    row_gemm<<<D1, 256>>>(memv, W0, r1, D0);    // r1 = tanh(mem)@W0^T (v1 frozen)
    row_gemm<<<D1, 256>>>(r1, W1, r2, D1);      // r2 = tanh(r1)@W1^T  (v2(0) row)
    row_gemm<<<D1, 256>>>(r2, W2, r3, D1);      // r3 = tanh(r2)@W2^T  (pred(0) row)
    e3_init<<<1024, 256>>>(corrupt, r3, M.v3, M.E3, M.E3f, D1 - 1,
                           (long)BROWS * D1);
    zero_ctr<<<(NCTR + 255) / 256, 256>>>(ctr, NCTR);

    // --------------- the whole 19-iteration loop in ONE launch -------------
    gemm_mega<<<GRID_MEGA, 256, SMEM_BYTES>>>(M);
}